// round 9
// baseline (speedup 1.0000x reference)
#include <cuda_runtime.h>
#include <cuda_fp16.h>
#include <cstdint>

// Problem constants (fixed by the dataset)
#define NN   50000
#define EE   1600000
#define EN   1650000      // EE + NN self loops
#define IND  256
#define HID  256
#define OUTD 48
#define KHOP 10
#define NBS  196          // ceil(NN/256) scan blocks

typedef unsigned long long u64;

// Packed fp32x2 FMA: d = a*b + d (elementwise on 2 packed floats)
#define FMA2(acc, a, b) \
    asm("fma.rn.f32x2 %0, %1, %2, %0;" : "+l"(acc) : "l"(a), "l"(b))
#define PACK_DUP(out, f) do { \
    unsigned _u = __float_as_uint(f); \
    asm("mov.b64 %0, {%1, %1};" : "=l"(out) : "r"(_u)); \
} while (0)
#define UNPACK2(lo, hi, in) \
    asm("mov.b64 {%0, %1}, %2;" : "=r"(lo), "=r"(hi) : "l"(in))

// ---------------- scratch (device globals; no allocation allowed) ----------
__device__ float     g_relu[NN * HID];    // relu(x@W1+b1)
__device__ float     g_h[NN * OUTD];      // MLP output h (fp32)
__device__ uint2     g_rf0[NN * 12];      // fp16 r ping (48 halves per node)
__device__ uint2     g_rf1[NN * 12];      // fp16 r pong
__device__ int       g_deg[NN];
__device__ int       g_scan[NN];
__device__ int       g_bsum[256];
__device__ int       g_boff[256];
__device__ int       g_rowptr[NN + 1];
__device__ int       g_cursor[NN];
__device__ float     g_dinv[NN];
__device__ long long g_edges[EN];         // packed {src:int32 (lo), norm:f32 (hi)}

// ---------------- CSR build -------------------------------------------------
__global__ void k_init_deg() {
    int i = blockIdx.x * blockDim.x + threadIdx.x;
    if (i < NN) g_deg[i] = 1;   // self loop
}

__global__ void k_count(const int* __restrict__ ei) {
    int i = blockIdx.x * blockDim.x + threadIdx.x;
    if (i < EE) {
        int d = ei[EE + i];
        if ((unsigned)d < NN) atomicAdd(&g_deg[d], 1);
    }
}

__global__ void k_scan1() {
    __shared__ int s[256];
    int tx = threadIdx.x;
    int i = blockIdx.x * 256 + tx;
    int v = (i < NN) ? g_deg[i] : 0;
    s[tx] = v;
    __syncthreads();
    #pragma unroll
    for (int off = 1; off < 256; off <<= 1) {
        int add = (tx >= off) ? s[tx - off] : 0;
        __syncthreads();
        s[tx] += add;
        __syncthreads();
    }
    if (i < NN) g_scan[i] = s[tx];
    if (tx == 255) g_bsum[blockIdx.x] = s[255];
}

__global__ void k_scan2() {
    __shared__ int s[256];
    int tx = threadIdx.x;
    int v = (tx < NBS) ? g_bsum[tx] : 0;
    s[tx] = v;
    __syncthreads();
    #pragma unroll
    for (int off = 1; off < 256; off <<= 1) {
        int add = (tx >= off) ? s[tx - off] : 0;
        __syncthreads();
        s[tx] += add;
        __syncthreads();
    }
    g_boff[tx] = s[tx] - v;   // exclusive
}

__global__ void k_scan3() {
    int i = blockIdx.x * blockDim.x + threadIdx.x;
    if (i >= NN) return;
    int incl = g_scan[i] + g_boff[i >> 8];
    g_rowptr[i + 1] = incl;
    g_cursor[i] = incl - g_deg[i];           // exclusive start
    g_dinv[i] = rsqrtf((float)g_deg[i]);     // deg >= 1 always
    if (i == 0) g_rowptr[0] = 0;
}

__global__ void k_fill(const int* __restrict__ ei) {
    int i = blockIdx.x * blockDim.x + threadIdx.x;
    if (i >= EN) return;
    int s, d;
    if (i < EE) { s = ei[i]; d = ei[EE + i]; }
    else        { s = i - EE; d = s; }
    if ((unsigned)s >= NN || (unsigned)d >= NN) return;
    float w = g_dinv[s] * g_dinv[d];
    int pos = atomicAdd(&g_cursor[d], 1);
    g_edges[pos] = (long long)(unsigned)s |
                   ((long long)__float_as_uint(w) << 32);
}

// ---------------- GEMM1: g_relu = relu(x @ W1 + b1) -------------------------
// 128x128 tile, 256 threads, 8x8 per thread, packed f32x2 FMAs.
// A stored in smem PRE-DUPLICATED ({a,a} u64) so the inner loop is pure
// LDS.128 -> FMA2 with zero pack movs. Double-buffered.
#define KC 16
__global__ void __launch_bounds__(256, 2)
k_gemm1(const float* __restrict__ A, const float* __restrict__ B,
        const float* __restrict__ bias) {
    __shared__ __align__(16) u64   Asd[2][KC][128];  // dup pairs, k-major
    __shared__ __align__(16) float Bs[2][KC][128];
    int tid  = threadIdx.x;
    int brow = blockIdx.y * 128;
    int bcol = blockIdx.x * 128;
    int tr = tid >> 4, tc = tid & 15;

    // A load: row = tid>>1, k-offset = (tid&1)*8 (two float4)
    int arow = tid >> 1;
    int ak   = (tid & 1) << 3;
    int grow = brow + arow;
    bool aok = grow < NN;
    const float* aptr = A + (size_t)grow * IND + ak;
    // B load: k-row = tid>>4, col-offset = (tid&15)*8
    int bk = tid >> 4;
    int bc = (tid & 15) << 3;
    const float* bptr = B + bk * HID + bcol + bc;

    float4 pa0, pa1, pb0, pb1;
    const float4 z4 = make_float4(0.f, 0.f, 0.f, 0.f);
    pa0 = aok ? *(const float4*)(aptr)     : z4;
    pa1 = aok ? *(const float4*)(aptr + 4) : z4;
    pb0 = *(const float4*)(bptr);
    pb1 = *(const float4*)(bptr + 4);

    u64 acc2[8][4];   // 8 rows x 4 col-pairs
    #pragma unroll
    for (int i = 0; i < 8; ++i)
        #pragma unroll
        for (int j = 0; j < 4; ++j) acc2[i][j] = 0ull;

    // Stage fill helper values
    {
        float av[8] = {pa0.x, pa0.y, pa0.z, pa0.w, pa1.x, pa1.y, pa1.z, pa1.w};
        #pragma unroll
        for (int kk = 0; kk < 8; ++kk) {
            u64 d; PACK_DUP(d, av[kk]);
            Asd[0][ak + kk][arow] = d;
        }
        *(float4*)&Bs[0][bk][bc]     = pb0;
        *(float4*)&Bs[0][bk][bc + 4] = pb1;
    }
    __syncthreads();

    #pragma unroll 1
    for (int c = 0; c < IND / KC; ++c) {
        int cur = c & 1;
        if (c + 1 < IND / KC) {
            const float* ap = aptr + (c + 1) * KC;
            pa0 = aok ? *(const float4*)(ap)     : z4;
            pa1 = aok ? *(const float4*)(ap + 4) : z4;
            const float* bp = bptr + (c + 1) * KC * HID;
            pb0 = *(const float4*)(bp);
            pb1 = *(const float4*)(bp + 4);
        }
        #pragma unroll
        for (int k = 0; k < KC; ++k) {
            // A dup-pairs: rows 4tr..4tr+3 and 64+4tr..64+4tr+3
            ulonglong2 aq0 = *(const ulonglong2*)&Asd[cur][k][tr << 2];
            ulonglong2 aq1 = *(const ulonglong2*)&Asd[cur][k][(tr << 2) + 2];
            ulonglong2 aq2 = *(const ulonglong2*)&Asd[cur][k][64 + (tr << 2)];
            ulonglong2 aq3 = *(const ulonglong2*)&Asd[cur][k][64 + (tr << 2) + 2];
            u64 av2[8] = {aq0.x, aq0.y, aq1.x, aq1.y,
                          aq2.x, aq2.y, aq3.x, aq3.y};
            // B pairs straight out of LDS.128 register pairs
            ulonglong2 bq0 = *(const ulonglong2*)&Bs[cur][k][tc << 2];
            ulonglong2 bq1 = *(const ulonglong2*)&Bs[cur][k][64 + (tc << 2)];
            u64 bp2[4] = {bq0.x, bq0.y, bq1.x, bq1.y};
            #pragma unroll
            for (int i = 0; i < 8; ++i)
                #pragma unroll
                for (int j = 0; j < 4; ++j) FMA2(acc2[i][j], av2[i], bp2[j]);
        }
        if (c + 1 < IND / KC) {
            int nxt = cur ^ 1;
            float av[8] = {pa0.x, pa0.y, pa0.z, pa0.w, pa1.x, pa1.y, pa1.z, pa1.w};
            #pragma unroll
            for (int kk = 0; kk < 8; ++kk) {
                u64 d; PACK_DUP(d, av[kk]);
                Asd[nxt][ak + kk][arow] = d;
            }
            *(float4*)&Bs[nxt][bk][bc]     = pb0;
            *(float4*)&Bs[nxt][bk][bc + 4] = pb1;
            __syncthreads();
        }
    }

    float4 bb0 = *(const float4*)(bias + bcol + (tc << 2));
    float4 bb1 = *(const float4*)(bias + bcol + 64 + (tc << 2));
    float bsv[8] = {bb0.x, bb0.y, bb0.z, bb0.w, bb1.x, bb1.y, bb1.z, bb1.w};
    #pragma unroll
    for (int half = 0; half < 2; ++half) {
        #pragma unroll
        for (int i = 0; i < 4; ++i) {
            int ii = half * 4 + i;
            int gr = brow + half * 64 + (tr << 2) + i;
            if (gr < NN) {
                float* orow = g_relu + (size_t)gr * HID + bcol;
                unsigned lo, hi;
                float v[8];
                #pragma unroll
                for (int j = 0; j < 4; ++j) {
                    UNPACK2(lo, hi, acc2[ii][j]);
                    v[2 * j]     = __uint_as_float(lo);
                    v[2 * j + 1] = __uint_as_float(hi);
                }
                float4 o0, o1;
                o0.x = fmaxf(v[0] + bsv[0], 0.f);
                o0.y = fmaxf(v[1] + bsv[1], 0.f);
                o0.z = fmaxf(v[2] + bsv[2], 0.f);
                o0.w = fmaxf(v[3] + bsv[3], 0.f);
                o1.x = fmaxf(v[4] + bsv[4], 0.f);
                o1.y = fmaxf(v[5] + bsv[5], 0.f);
                o1.z = fmaxf(v[6] + bsv[6], 0.f);
                o1.w = fmaxf(v[7] + bsv[7], 0.f);
                *(float4*)(orow + (tc << 2))      = o0;
                *(float4*)(orow + 64 + (tc << 2)) = o1;
            }
        }
    }
}

// ---------------- GEMM2: g_h = g_relu @ W2 + b2; seed r_K = temp[K]*h -------
// 256-row tile, 256 threads, 8 rows x 6 cols per thread, f32x2 FMAs.
#define G2KC 32
__global__ void __launch_bounds__(256)
k_gemm2(const float* __restrict__ W, const float* __restrict__ bias,
        const float* __restrict__ temp) {
    __shared__ __align__(16) float Ws[G2KC * 48];     // 6 KB
    __shared__ __align__(16) float As[G2KC * 260];    // k-major, pad 260
    int tid  = threadIdx.x;
    int row0 = blockIdx.x * 256;
    int rg = tid >> 3;    // 0..31 -> rows rg*8..rg*8+7
    int cg = tid & 7;     // cols cg*6..cg*6+5

    u64 acc2[8][3];
    #pragma unroll
    for (int i = 0; i < 8; ++i)
        #pragma unroll
        for (int j = 0; j < 3; ++j) acc2[i][j] = 0ull;

    for (int kb = 0; kb < HID; kb += G2KC) {
        __syncthreads();
        #pragma unroll
        for (int j = 0; j < 6; ++j) {
            int li = tid + j * 256;       // < 1536
            Ws[li] = W[kb * 48 + li];
        }
        #pragma unroll
        for (int j = 0; j < 8; ++j) {
            int f = tid + j * 256;        // < 2048
            int row = f >> 3;
            int q = f & 7;
            int gr = row0 + row;
            float4 v = (gr < NN) ? *(const float4*)(g_relu + (size_t)gr * HID + kb + q * 4)
                                 : make_float4(0.f, 0.f, 0.f, 0.f);
            As[(q * 4 + 0) * 260 + row] = v.x;
            As[(q * 4 + 1) * 260 + row] = v.y;
            As[(q * 4 + 2) * 260 + row] = v.z;
            As[(q * 4 + 3) * 260 + row] = v.w;
        }
        __syncthreads();
        #pragma unroll 4
        for (int k = 0; k < G2KC; ++k) {
            const float* wrow = Ws + k * 48 + cg * 6;
            u64 wp0 = *(const u64*)(wrow);
            u64 wp1 = *(const u64*)(wrow + 2);
            u64 wp2 = *(const u64*)(wrow + 4);
            float4 a0 = *(const float4*)&As[k * 260 + rg * 8];
            float4 a1 = *(const float4*)&As[k * 260 + rg * 8 + 4];
            float av[8] = {a0.x, a0.y, a0.z, a0.w, a1.x, a1.y, a1.z, a1.w};
            #pragma unroll
            for (int i = 0; i < 8; ++i) {
                u64 aa;
                PACK_DUP(aa, av[i]);
                FMA2(acc2[i][0], aa, wp0);
                FMA2(acc2[i][1], aa, wp1);
                FMA2(acc2[i][2], aa, wp2);
            }
        }
    }

    float tK = __ldg(temp + KHOP);     // (1-alpha)^K
    __half* rf = (__half*)g_rf0;
    float bs[6];
    #pragma unroll
    for (int j = 0; j < 6; ++j) bs[j] = bias[cg * 6 + j];
    #pragma unroll
    for (int i = 0; i < 8; ++i) {
        int gr = row0 + rg * 8 + i;
        if (gr < NN) {
            unsigned lo, hi;
            #pragma unroll
            for (int j = 0; j < 3; ++j) {
                UNPACK2(lo, hi, acc2[i][j]);
                float v0 = __uint_as_float(lo) + bs[2 * j];
                float v1 = __uint_as_float(hi) + bs[2 * j + 1];
                int c = cg * 6 + 2 * j;
                g_h[(size_t)gr * 48 + c]     = v0;
                g_h[(size_t)gr * 48 + c + 1] = v1;
                rf[(size_t)gr * 48 + c]     = __float2half_rn(tK * v0);
                rf[(size_t)gr * 48 + c + 1] = __float2half_rn(tK * v1);
            }
        }
    }
}

// ---------------- propagation (Horner): r_k = temp[k]*h + H r_{k+1} ---------
// 12 threads per node, uint2 (4 fp16) gathers — max chip-wide MLP (R3-proven).
__global__ void k_prop(const float* __restrict__ temp, int k, int srcbuf,
                       float* __restrict__ out) {
    int t = blockIdx.x * blockDim.x + threadIdx.x;
    int node = t / 12;
    if (node >= NN) return;
    int fx = t - node * 12;

    const uint2* __restrict__ cur = srcbuf ? g_rf1 : g_rf0;
    uint2*       __restrict__ nxt = srcbuf ? g_rf0 : g_rf1;

    int beg = g_rowptr[node], end = g_rowptr[node + 1];
    float4 acc = make_float4(0.f, 0.f, 0.f, 0.f);
    const int2* ed = (const int2*)g_edges;
    #pragma unroll 4
    for (int p = beg; p < end; ++p) {
        int2 e = ed[p];
        float w = __int_as_float(e.y);
        uint2 v = __ldg(&cur[e.x * 12 + fx]);
        __half2 h0 = *reinterpret_cast<__half2*>(&v.x);
        __half2 h1 = *reinterpret_cast<__half2*>(&v.y);
        float2 f0 = __half22float2(h0);
        float2 f1 = __half22float2(h1);
        acc.x = fmaf(w, f0.x, acc.x);
        acc.y = fmaf(w, f0.y, acc.y);
        acc.z = fmaf(w, f1.x, acc.z);
        acc.w = fmaf(w, f1.y, acc.w);
    }
    float g = __ldg(temp + k);
    float4 hv = *(const float4*)(g_h + (size_t)node * 48 + fx * 4);
    float4 r;
    r.x = fmaf(g, hv.x, acc.x);
    r.y = fmaf(g, hv.y, acc.y);
    r.z = fmaf(g, hv.z, acc.z);
    r.w = fmaf(g, hv.w, acc.w);
    if (k == 0) {
        *(float4*)(out + (size_t)node * 48 + fx * 4) = r;
    } else {
        __half2 o0 = __floats2half2_rn(r.x, r.y);
        __half2 o1 = __floats2half2_rn(r.z, r.w);
        uint2 o;
        o.x = *reinterpret_cast<unsigned*>(&o0);
        o.y = *reinterpret_cast<unsigned*>(&o1);
        nxt[node * 12 + fx] = o;
    }
}

// ---------------- log_softmax (in place on d_out) ---------------------------
__global__ void k_lsm(float* __restrict__ out) {
    int gt = blockIdx.x * blockDim.x + threadIdx.x;
    int row = gt >> 5;
    int lane = gt & 31;
    if (row >= NN) return;
    float* r = out + (size_t)row * 48;
    float v0 = r[lane];
    float v1 = (lane < 16) ? r[32 + lane] : -3.4e38f;
    float m = fmaxf(v0, v1);
    #pragma unroll
    for (int s = 16; s; s >>= 1) m = fmaxf(m, __shfl_xor_sync(0xffffffffu, m, s));
    float e = expf(v0 - m) + ((lane < 16) ? expf(v1 - m) : 0.f);
    #pragma unroll
    for (int s = 16; s; s >>= 1) e += __shfl_xor_sync(0xffffffffu, e, s);
    float lse = m + logf(e);
    r[lane] = v0 - lse;
    if (lane < 16) r[32 + lane] = v1 - lse;
}

// ---------------- launch ----------------------------------------------------
extern "C" void kernel_launch(void* const* d_in, const int* in_sizes, int n_in,
                              void* d_out, int out_size) {
    const float* x    = (const float*)d_in[0];
    const int*   ei   = (const int*)d_in[1];      // int32 [2, EE]
    const float* W1   = (const float*)d_in[2];
    const float* b1   = (const float*)d_in[3];
    const float* W2   = (const float*)d_in[4];
    const float* b2   = (const float*)d_in[5];
    const float* temp = (const float*)d_in[6];
    float* out = (float*)d_out;
    (void)in_sizes; (void)n_in; (void)out_size;

    // k_gemm1 is launch #4 — the slot the fixed ncu window captures.
    k_init_deg<<<(NN + 255) / 256, 256>>>();              // 1
    k_count<<<(EE + 255) / 256, 256>>>(ei);               // 2
    k_scan1<<<NBS, 256>>>();                              // 3
    dim3 g1((HID + 127) / 128, (NN + 127) / 128);
    k_gemm1<<<g1, 256>>>(x, W1, b1);                      // 4  <- profiled
    k_scan2<<<1, 256>>>();                                // 5
    k_scan3<<<NBS, 256>>>();                              // 6
    k_fill<<<(EE + NN + 255) / 256, 256>>>(ei);           // 7
    k_gemm2<<<(NN + 255) / 256, 256>>>(W2, b2, temp);     // 8

    // Horner propagation: r_k = temp[k]*h + H r_{k+1}, k = K-1 .. 0
    for (int k = KHOP - 1; k >= 0; --k) {
        int s = KHOP - k;                       // step number 1..K
        int srcbuf = (s & 1) ? 0 : 1;           // r_{k+1} location
        k_prop<<<(NN * 12 + 191) / 192, 192>>>(temp, k, srcbuf, out);
    }

    k_lsm<<<(NN + 7) / 8, 256>>>(out);
}

// round 11
// speedup vs baseline: 1.0877x; 1.0877x over previous
#include <cuda_runtime.h>
#include <cuda_fp16.h>
#include <cstdint>

// Problem constants (fixed by the dataset)
#define NN   50000
#define EE   1600000
#define EN   1650000      // EE + NN self loops
#define IND  256
#define HID  256
#define OUTD 48
#define KHOP 10
#define NBS  196          // ceil(NN/256) scan blocks

typedef unsigned long long u64;

// Packed fp32x2 FMA: d = a*b + d (elementwise on 2 packed floats)
#define FMA2(acc, a, b) \
    asm("fma.rn.f32x2 %0, %1, %2, %0;" : "+l"(acc) : "l"(a), "l"(b))
#define PACK_DUP(out, f) do { \
    unsigned _u = __float_as_uint(f); \
    asm("mov.b64 %0, {%1, %1};" : "=l"(out) : "r"(_u)); \
} while (0)
#define UNPACK2(lo, hi, in) \
    asm("mov.b64 {%0, %1}, %2;" : "=r"(lo), "=r"(hi) : "l"(in))

// ---------------- scratch (device globals; no allocation allowed) ----------
__device__ float     g_relu[NN * HID];    // relu(x@W1+b1)
__device__ float     g_h[NN * OUTD];      // MLP output h (fp32)
__device__ uint2     g_rf0[NN * 12];      // fp16 r ping (48 halves per node)
__device__ uint2     g_rf1[NN * 12];      // fp16 r pong
__device__ int       g_deg[NN];
__device__ int       g_scan[NN];
__device__ int       g_bsum[256];
__device__ int       g_rowptr[NN + 1];
__device__ int       g_cursor[NN];
__device__ float     g_dinv[NN];
__device__ long long g_edges[EN];         // packed {src:int32 (lo), norm:f32 (hi)}

// ---------------- CSR build -------------------------------------------------
__global__ void k_init_deg() {
    int i = blockIdx.x * blockDim.x + threadIdx.x;
    if (i < NN) g_deg[i] = 1;   // self loop
}

__global__ void k_count(const int* __restrict__ ei) {
    int i = blockIdx.x * blockDim.x + threadIdx.x;
    if (i < EE) {
        int d = ei[EE + i];
        if ((unsigned)d < NN) atomicAdd(&g_deg[d], 1);
    }
}

__global__ void k_scan1() {
    __shared__ int s[256];
    int tx = threadIdx.x;
    int i = blockIdx.x * 256 + tx;
    int v = (i < NN) ? g_deg[i] : 0;
    s[tx] = v;
    __syncthreads();
    #pragma unroll
    for (int off = 1; off < 256; off <<= 1) {
        int add = (tx >= off) ? s[tx - off] : 0;
        __syncthreads();
        s[tx] += add;
        __syncthreads();
    }
    if (i < NN) g_scan[i] = s[tx];
    if (tx == 255) g_bsum[blockIdx.x] = s[255];
}

// scan of block sums fused in: each block redundantly scans g_bsum in smem
// and extracts its own exclusive offset (kills the old single-block k_scan2).
__global__ void k_scan3() {
    __shared__ int s[256];
    int tx = threadIdx.x;
    int b  = blockIdx.x;
    int bv = (tx < NBS) ? g_bsum[tx] : 0;
    s[tx] = bv;
    __syncthreads();
    #pragma unroll
    for (int off = 1; off < 256; off <<= 1) {
        int add = (tx >= off) ? s[tx - off] : 0;
        __syncthreads();
        s[tx] += add;
        __syncthreads();
    }
    int boff = s[b] - g_bsum[b];   // exclusive offset of this block's chunk
    int i = b * 256 + tx;
    if (i >= NN) return;
    int incl = g_scan[i] + boff;
    g_rowptr[i + 1] = incl;
    g_cursor[i] = incl - g_deg[i];           // exclusive start
    g_dinv[i] = rsqrtf((float)g_deg[i]);     // deg >= 1 always
    if (i == 0) g_rowptr[0] = 0;
}

__global__ void k_fill(const int* __restrict__ ei) {
    int i = blockIdx.x * blockDim.x + threadIdx.x;
    if (i >= EN) return;
    int s, d;
    if (i < EE) { s = ei[i]; d = ei[EE + i]; }
    else        { s = i - EE; d = s; }
    if ((unsigned)s >= NN || (unsigned)d >= NN) return;
    float w = g_dinv[s] * g_dinv[d];
    int pos = atomicAdd(&g_cursor[d], 1);
    g_edges[pos] = (long long)(unsigned)s |
                   ((long long)__float_as_uint(w) << 32);
}

// ---------------- GEMM1: g_relu = relu(x @ W1 + b1) -------------------------
// 128x128 tile, 256 threads, 8x8 per thread, packed f32x2 FMAs.
// (R7 configuration — best measured: 144.8 us.)
#define KC 16
__global__ void __launch_bounds__(256, 2)
k_gemm1(const float* __restrict__ A, const float* __restrict__ B,
        const float* __restrict__ bias) {
    __shared__ __align__(16) float As[KC][132];   // transposed A tile (k-major)
    __shared__ __align__(16) float Bs[KC][132];
    int tid  = threadIdx.x;
    int brow = blockIdx.y * 128;
    int bcol = blockIdx.x * 128;
    int tr = tid >> 4, tc = tid & 15;

    // A load: row = tid>>1, k-offset = (tid&1)*8 (two float4)
    int arow = tid >> 1;
    int ak   = (tid & 1) << 3;
    int grow = brow + arow;
    bool aok = grow < NN;
    const float* aptr = A + (size_t)grow * IND + ak;
    // B load: k-row = tid>>4, col-offset = (tid&15)*8
    int bk = tid >> 4;
    int bc = (tid & 15) << 3;
    const float* bptr = B + bk * HID + bcol + bc;

    float4 pa0, pa1, pb0, pb1;
    const float4 z4 = make_float4(0.f, 0.f, 0.f, 0.f);
    pa0 = aok ? *(const float4*)(aptr)     : z4;
    pa1 = aok ? *(const float4*)(aptr + 4) : z4;
    pb0 = *(const float4*)(bptr);
    pb1 = *(const float4*)(bptr + 4);

    u64 acc2[8][4];   // 8 rows x 4 col-pairs
    #pragma unroll
    for (int i = 0; i < 8; ++i)
        #pragma unroll
        for (int j = 0; j < 4; ++j) acc2[i][j] = 0ull;

    #pragma unroll 1
    for (int c = 0; c < IND / KC; ++c) {
        __syncthreads();
        As[ak + 0][arow] = pa0.x;
        As[ak + 1][arow] = pa0.y;
        As[ak + 2][arow] = pa0.z;
        As[ak + 3][arow] = pa0.w;
        As[ak + 4][arow] = pa1.x;
        As[ak + 5][arow] = pa1.y;
        As[ak + 6][arow] = pa1.z;
        As[ak + 7][arow] = pa1.w;
        *(float4*)&Bs[bk][bc]     = pb0;
        *(float4*)&Bs[bk][bc + 4] = pb1;
        __syncthreads();
        if (c + 1 < IND / KC) {
            const float* ap = aptr + (c + 1) * KC;
            pa0 = aok ? *(const float4*)(ap)     : z4;
            pa1 = aok ? *(const float4*)(ap + 4) : z4;
            const float* bp = bptr + (c + 1) * KC * HID;
            pb0 = *(const float4*)(bp);
            pb1 = *(const float4*)(bp + 4);
        }
        #pragma unroll
        for (int k = 0; k < KC; ++k) {
            float4 a0 = *(const float4*)&As[k][tr << 2];
            float4 a1 = *(const float4*)&As[k][64 + (tr << 2)];
            // B pairs straight out of LDS.128 register pairs (no repack)
            ulonglong2 bq0 = *(const ulonglong2*)&Bs[k][tc << 2];
            ulonglong2 bq1 = *(const ulonglong2*)&Bs[k][64 + (tc << 2)];
            u64 bp2[4] = {bq0.x, bq0.y, bq1.x, bq1.y};
            float av[8] = {a0.x, a0.y, a0.z, a0.w, a1.x, a1.y, a1.z, a1.w};
            #pragma unroll
            for (int i = 0; i < 8; ++i) {
                u64 aa;
                PACK_DUP(aa, av[i]);
                #pragma unroll
                for (int j = 0; j < 4; ++j) FMA2(acc2[i][j], aa, bp2[j]);
            }
        }
    }

    float4 bb0 = *(const float4*)(bias + bcol + (tc << 2));
    float4 bb1 = *(const float4*)(bias + bcol + 64 + (tc << 2));
    float bsv[8] = {bb0.x, bb0.y, bb0.z, bb0.w, bb1.x, bb1.y, bb1.z, bb1.w};
    #pragma unroll
    for (int half = 0; half < 2; ++half) {
        #pragma unroll
        for (int i = 0; i < 4; ++i) {
            int ii = half * 4 + i;
            int gr = brow + half * 64 + (tr << 2) + i;
            if (gr < NN) {
                float* orow = g_relu + (size_t)gr * HID + bcol;
                unsigned lo, hi;
                float v[8];
                #pragma unroll
                for (int j = 0; j < 4; ++j) {
                    UNPACK2(lo, hi, acc2[ii][j]);
                    v[2 * j]     = __uint_as_float(lo);
                    v[2 * j + 1] = __uint_as_float(hi);
                }
                float4 o0, o1;
                o0.x = fmaxf(v[0] + bsv[0], 0.f);
                o0.y = fmaxf(v[1] + bsv[1], 0.f);
                o0.z = fmaxf(v[2] + bsv[2], 0.f);
                o0.w = fmaxf(v[3] + bsv[3], 0.f);
                o1.x = fmaxf(v[4] + bsv[4], 0.f);
                o1.y = fmaxf(v[5] + bsv[5], 0.f);
                o1.z = fmaxf(v[6] + bsv[6], 0.f);
                o1.w = fmaxf(v[7] + bsv[7], 0.f);
                *(float4*)(orow + (tc << 2))      = o0;
                *(float4*)(orow + 64 + (tc << 2)) = o1;
            }
        }
    }
}

// ---------------- GEMM2: g_h = g_relu @ W2 + b2; seed r_K = temp[K]*h -------
// 256-row tile, 256 threads, 8 rows x 6 cols per thread, f32x2 FMAs.
#define G2KC 32
__global__ void __launch_bounds__(256)
k_gemm2(const float* __restrict__ W, const float* __restrict__ bias,
        const float* __restrict__ temp) {
    __shared__ __align__(16) float Ws[G2KC * 48];     // 6 KB
    __shared__ __align__(16) float As[G2KC * 260];    // k-major, pad 260
    int tid  = threadIdx.x;
    int row0 = blockIdx.x * 256;
    int rg = tid >> 3;    // 0..31 -> rows rg*8..rg*8+7
    int cg = tid & 7;     // cols cg*6..cg*6+5

    u64 acc2[8][3];
    #pragma unroll
    for (int i = 0; i < 8; ++i)
        #pragma unroll
        for (int j = 0; j < 3; ++j) acc2[i][j] = 0ull;

    for (int kb = 0; kb < HID; kb += G2KC) {
        __syncthreads();
        #pragma unroll
        for (int j = 0; j < 6; ++j) {
            int li = tid + j * 256;       // < 1536
            Ws[li] = W[kb * 48 + li];
        }
        #pragma unroll
        for (int j = 0; j < 8; ++j) {
            int f = tid + j * 256;        // < 2048
            int row = f >> 3;
            int q = f & 7;
            int gr = row0 + row;
            float4 v = (gr < NN) ? *(const float4*)(g_relu + (size_t)gr * HID + kb + q * 4)
                                 : make_float4(0.f, 0.f, 0.f, 0.f);
            As[(q * 4 + 0) * 260 + row] = v.x;
            As[(q * 4 + 1) * 260 + row] = v.y;
            As[(q * 4 + 2) * 260 + row] = v.z;
            As[(q * 4 + 3) * 260 + row] = v.w;
        }
        __syncthreads();
        #pragma unroll 4
        for (int k = 0; k < G2KC; ++k) {
            const float* wrow = Ws + k * 48 + cg * 6;
            u64 wp0 = *(const u64*)(wrow);
            u64 wp1 = *(const u64*)(wrow + 2);
            u64 wp2 = *(const u64*)(wrow + 4);
            float4 a0 = *(const float4*)&As[k * 260 + rg * 8];
            float4 a1 = *(const float4*)&As[k * 260 + rg * 8 + 4];
            float av[8] = {a0.x, a0.y, a0.z, a0.w, a1.x, a1.y, a1.z, a1.w};
            #pragma unroll
            for (int i = 0; i < 8; ++i) {
                u64 aa;
                PACK_DUP(aa, av[i]);
                FMA2(acc2[i][0], aa, wp0);
                FMA2(acc2[i][1], aa, wp1);
                FMA2(acc2[i][2], aa, wp2);
            }
        }
    }

    float tK = __ldg(temp + KHOP);     // (1-alpha)^K
    __half* rf = (__half*)g_rf0;
    float bs[6];
    #pragma unroll
    for (int j = 0; j < 6; ++j) bs[j] = bias[cg * 6 + j];
    #pragma unroll
    for (int i = 0; i < 8; ++i) {
        int gr = row0 + rg * 8 + i;
        if (gr < NN) {
            unsigned lo, hi;
            #pragma unroll
            for (int j = 0; j < 3; ++j) {
                UNPACK2(lo, hi, acc2[i][j]);
                float v0 = __uint_as_float(lo) + bs[2 * j];
                float v1 = __uint_as_float(hi) + bs[2 * j + 1];
                int c = cg * 6 + 2 * j;
                g_h[(size_t)gr * 48 + c]     = v0;
                g_h[(size_t)gr * 48 + c + 1] = v1;
                rf[(size_t)gr * 48 + c]     = __float2half_rn(tK * v0);
                rf[(size_t)gr * 48 + c + 1] = __float2half_rn(tK * v1);
            }
        }
    }
}

// ---------------- propagation (Horner): r_k = temp[k]*h + H r_{k+1} ---------
// 12 threads per node, uint2 (4 fp16) gathers. Grid is exactly NN*12 threads
// (3125 blocks x 192), so every 12-thread group is full — the k==0 step fuses
// log-softmax via block smem and writes the final output directly.
__global__ void __launch_bounds__(192)
k_prop(const float* __restrict__ temp, int k, int srcbuf,
       float* __restrict__ out) {
    int tid  = threadIdx.x;
    int t    = blockIdx.x * 192 + tid;
    int node = t / 12;
    int fx   = t - node * 12;
    int ln   = tid / 12;          // node slot within block (0..15)

    const uint2* __restrict__ cur = srcbuf ? g_rf1 : g_rf0;
    uint2*       __restrict__ nxt = srcbuf ? g_rf0 : g_rf1;

    int beg = g_rowptr[node], end = g_rowptr[node + 1];
    float4 acc = make_float4(0.f, 0.f, 0.f, 0.f);
    const int2* ed = (const int2*)g_edges;
    #pragma unroll 4
    for (int p = beg; p < end; ++p) {
        int2 e = ed[p];
        float w = __int_as_float(e.y);
        uint2 v = __ldg(&cur[e.x * 12 + fx]);
        __half2 h0 = *reinterpret_cast<__half2*>(&v.x);
        __half2 h1 = *reinterpret_cast<__half2*>(&v.y);
        float2 f0 = __half22float2(h0);
        float2 f1 = __half22float2(h1);
        acc.x = fmaf(w, f0.x, acc.x);
        acc.y = fmaf(w, f0.y, acc.y);
        acc.z = fmaf(w, f1.x, acc.z);
        acc.w = fmaf(w, f1.y, acc.w);
    }
    float g = __ldg(temp + k);
    float4 hv = *(const float4*)(g_h + (size_t)node * 48 + fx * 4);
    float4 r;
    r.x = fmaf(g, hv.x, acc.x);
    r.y = fmaf(g, hv.y, acc.y);
    r.z = fmaf(g, hv.z, acc.z);
    r.w = fmaf(g, hv.w, acc.w);

    if (k != 0) {
        __half2 o0 = __floats2half2_rn(r.x, r.y);
        __half2 o1 = __floats2half2_rn(r.z, r.w);
        uint2 o;
        o.x = *reinterpret_cast<unsigned*>(&o0);
        o.y = *reinterpret_cast<unsigned*>(&o1);
        nxt[node * 12 + fx] = o;
        return;
    }

    // ---- k == 0: fused log-softmax over the node's 48 values ----
    __shared__ float pm[16][12];
    __shared__ float ps[16][12];
    __shared__ float red[16];
    float lmax = fmaxf(fmaxf(r.x, r.y), fmaxf(r.z, r.w));
    pm[ln][fx] = lmax;
    __syncthreads();
    if (fx == 0) {
        float m = pm[ln][0];
        #pragma unroll
        for (int j = 1; j < 12; ++j) m = fmaxf(m, pm[ln][j]);
        red[ln] = m;
    }
    __syncthreads();
    float m = red[ln];
    float es = expf(r.x - m) + expf(r.y - m) + expf(r.z - m) + expf(r.w - m);
    ps[ln][fx] = es;
    __syncthreads();
    if (fx == 0) {
        float ssum = 0.f;
        #pragma unroll
        for (int j = 0; j < 12; ++j) ssum += ps[ln][j];
        red[ln] = m + logf(ssum);
    }
    __syncthreads();
    float lse = red[ln];
    float4 o;
    o.x = r.x - lse;
    o.y = r.y - lse;
    o.z = r.z - lse;
    o.w = r.w - lse;
    *(float4*)(out + (size_t)node * 48 + fx * 4) = o;
}

// ---------------- launch ----------------------------------------------------
extern "C" void kernel_launch(void* const* d_in, const int* in_sizes, int n_in,
                              void* d_out, int out_size) {
    const float* x    = (const float*)d_in[0];
    const int*   ei   = (const int*)d_in[1];      // int32 [2, EE]
    const float* W1   = (const float*)d_in[2];
    const float* b1   = (const float*)d_in[3];
    const float* W2   = (const float*)d_in[4];
    const float* b2   = (const float*)d_in[5];
    const float* temp = (const float*)d_in[6];
    float* out = (float*)d_out;
    (void)in_sizes; (void)n_in; (void)out_size;

    // k_gemm2 is launch #4 — the slot the fixed ncu window captures.
    k_init_deg<<<(NN + 255) / 256, 256>>>();              // 1
    k_count<<<(EE + 255) / 256, 256>>>(ei);               // 2
    dim3 g1((HID + 127) / 128, (NN + 127) / 128);
    k_gemm1<<<g1, 256>>>(x, W1, b1);                      // 3
    k_gemm2<<<(NN + 255) / 256, 256>>>(W2, b2, temp);     // 4  <- profiled
    k_scan1<<<NBS, 256>>>();                              // 5
    k_scan3<<<NBS, 256>>>();                              // 6 (fused scan2+scan3)
    k_fill<<<(EE + NN + 255) / 256, 256>>>(ei);           // 7

    // Horner propagation: r_k = temp[k]*h + H r_{k+1}, k = K-1 .. 0
    // (k = 0 writes log-softmaxed output directly)
    for (int k = KHOP - 1; k >= 0; --k) {
        int s = KHOP - k;                       // step number 1..K
        int srcbuf = (s & 1) ? 0 : 1;           // r_{k+1} location
        k_prop<<<(NN * 12) / 192, 192>>>(temp, k, srcbuf, out);
    }
}

// round 13
// speedup vs baseline: 1.1621x; 1.0684x over previous
#include <cuda_runtime.h>
#include <cuda_fp16.h>
#include <cstdint>

// Problem constants (fixed by the dataset)
#define NN   50000
#define EE   1600000
#define EN   1650000      // EE + NN self loops
#define IND  256
#define HID  256
#define OUTD 48
#define KHOP 10
#define NBS  196          // ceil(NN/256) scan blocks

typedef unsigned long long u64;

// Packed fp32x2 FMA: d = a*b + d (elementwise on 2 packed floats)
#define FMA2(acc, a, b) \
    asm("fma.rn.f32x2 %0, %1, %2, %0;" : "+l"(acc) : "l"(a), "l"(b))
#define PACK_DUP(out, f) do { \
    unsigned _u = __float_as_uint(f); \
    asm("mov.b64 %0, {%1, %1};" : "=l"(out) : "r"(_u)); \
} while (0)
#define UNPACK2(lo, hi, in) \
    asm("mov.b64 {%0, %1}, %2;" : "=r"(lo), "=r"(hi) : "l"(in))

// ---------------- scratch (device globals; no allocation allowed) ----------
__device__ float     g_relu[NN * HID];    // relu(x@W1+b1)
__device__ float     g_h[NN * OUTD];      // MLP output h (fp32)
__device__ uint2     g_rf0[NN * 12];      // fp16 r ping (48 halves per node)
__device__ uint2     g_rf1[NN * 12];      // fp16 r pong
__device__ int       g_deg[NN];
__device__ int       g_scan[NN];
__device__ int       g_bsum[256];
__device__ int       g_rowptr[NN + 1];
__device__ int       g_cursor[NN];
__device__ float     g_dinv[NN];
__device__ long long g_edges[EN];         // packed {src:int32 (lo), norm:f32 (hi)}

// ---------------- CSR build -------------------------------------------------
__global__ void k_init_deg() {
    int i = blockIdx.x * blockDim.x + threadIdx.x;
    if (i < NN) g_deg[i] = 1;   // self loop
}

__global__ void k_count(const int* __restrict__ ei) {
    int i = blockIdx.x * blockDim.x + threadIdx.x;
    if (i < EE) {
        int d = ei[EE + i];
        if ((unsigned)d < NN) atomicAdd(&g_deg[d], 1);
    }
}

__global__ void k_scan1() {
    __shared__ int s[256];
    int tx = threadIdx.x;
    int i = blockIdx.x * 256 + tx;
    int v = (i < NN) ? g_deg[i] : 0;
    s[tx] = v;
    __syncthreads();
    #pragma unroll
    for (int off = 1; off < 256; off <<= 1) {
        int add = (tx >= off) ? s[tx - off] : 0;
        __syncthreads();
        s[tx] += add;
        __syncthreads();
    }
    if (i < NN) g_scan[i] = s[tx];
    if (tx == 255) g_bsum[blockIdx.x] = s[255];
}

// scan of block sums fused in: each block redundantly scans g_bsum in smem
// and extracts its own exclusive offset.
__global__ void k_scan3() {
    __shared__ int s[256];
    int tx = threadIdx.x;
    int b  = blockIdx.x;
    int bv = (tx < NBS) ? g_bsum[tx] : 0;
    s[tx] = bv;
    __syncthreads();
    #pragma unroll
    for (int off = 1; off < 256; off <<= 1) {
        int add = (tx >= off) ? s[tx - off] : 0;
        __syncthreads();
        s[tx] += add;
        __syncthreads();
    }
    int boff = s[b] - g_bsum[b];   // exclusive offset of this block's chunk
    int i = b * 256 + tx;
    if (i >= NN) return;
    int incl = g_scan[i] + boff;
    g_rowptr[i + 1] = incl;
    g_cursor[i] = incl - g_deg[i];           // exclusive start
    g_dinv[i] = rsqrtf((float)g_deg[i]);     // deg >= 1 always
    if (i == 0) g_rowptr[0] = 0;
}

__global__ void k_fill(const int* __restrict__ ei) {
    int i = blockIdx.x * blockDim.x + threadIdx.x;
    if (i >= EN) return;
    int s, d;
    if (i < EE) { s = ei[i]; d = ei[EE + i]; }
    else        { s = i - EE; d = s; }
    if ((unsigned)s >= NN || (unsigned)d >= NN) return;
    float w = g_dinv[s] * g_dinv[d];
    int pos = atomicAdd(&g_cursor[d], 1);
    g_edges[pos] = (long long)(unsigned)s |
                   ((long long)__float_as_uint(w) << 32);
}

// ---------------- GEMM1: g_relu = relu(x @ W1 + b1) -------------------------
// 128x128 tile, 256 threads, 8x8 per thread, packed f32x2 FMAs.
// (R7 configuration — best measured: 144.8 us.)
#define KC 16
__global__ void __launch_bounds__(256, 2)
k_gemm1(const float* __restrict__ A, const float* __restrict__ B,
        const float* __restrict__ bias) {
    __shared__ __align__(16) float As[KC][132];   // transposed A tile (k-major)
    __shared__ __align__(16) float Bs[KC][132];
    int tid  = threadIdx.x;
    int brow = blockIdx.y * 128;
    int bcol = blockIdx.x * 128;
    int tr = tid >> 4, tc = tid & 15;

    int arow = tid >> 1;
    int ak   = (tid & 1) << 3;
    int grow = brow + arow;
    bool aok = grow < NN;
    const float* aptr = A + (size_t)grow * IND + ak;
    int bk = tid >> 4;
    int bc = (tid & 15) << 3;
    const float* bptr = B + bk * HID + bcol + bc;

    float4 pa0, pa1, pb0, pb1;
    const float4 z4 = make_float4(0.f, 0.f, 0.f, 0.f);
    pa0 = aok ? *(const float4*)(aptr)     : z4;
    pa1 = aok ? *(const float4*)(aptr + 4) : z4;
    pb0 = *(const float4*)(bptr);
    pb1 = *(const float4*)(bptr + 4);

    u64 acc2[8][4];   // 8 rows x 4 col-pairs
    #pragma unroll
    for (int i = 0; i < 8; ++i)
        #pragma unroll
        for (int j = 0; j < 4; ++j) acc2[i][j] = 0ull;

    #pragma unroll 1
    for (int c = 0; c < IND / KC; ++c) {
        __syncthreads();
        As[ak + 0][arow] = pa0.x;
        As[ak + 1][arow] = pa0.y;
        As[ak + 2][arow] = pa0.z;
        As[ak + 3][arow] = pa0.w;
        As[ak + 4][arow] = pa1.x;
        As[ak + 5][arow] = pa1.y;
        As[ak + 6][arow] = pa1.z;
        As[ak + 7][arow] = pa1.w;
        *(float4*)&Bs[bk][bc]     = pb0;
        *(float4*)&Bs[bk][bc + 4] = pb1;
        __syncthreads();
        if (c + 1 < IND / KC) {
            const float* ap = aptr + (c + 1) * KC;
            pa0 = aok ? *(const float4*)(ap)     : z4;
            pa1 = aok ? *(const float4*)(ap + 4) : z4;
            const float* bp = bptr + (c + 1) * KC * HID;
            pb0 = *(const float4*)(bp);
            pb1 = *(const float4*)(bp + 4);
        }
        #pragma unroll
        for (int k = 0; k < KC; ++k) {
            float4 a0 = *(const float4*)&As[k][tr << 2];
            float4 a1 = *(const float4*)&As[k][64 + (tr << 2)];
            ulonglong2 bq0 = *(const ulonglong2*)&Bs[k][tc << 2];
            ulonglong2 bq1 = *(const ulonglong2*)&Bs[k][64 + (tc << 2)];
            u64 bp2[4] = {bq0.x, bq0.y, bq1.x, bq1.y};
            float av[8] = {a0.x, a0.y, a0.z, a0.w, a1.x, a1.y, a1.z, a1.w};
            #pragma unroll
            for (int i = 0; i < 8; ++i) {
                u64 aa;
                PACK_DUP(aa, av[i]);
                #pragma unroll
                for (int j = 0; j < 4; ++j) FMA2(acc2[i][j], aa, bp2[j]);
            }
        }
    }

    float4 bb0 = *(const float4*)(bias + bcol + (tc << 2));
    float4 bb1 = *(const float4*)(bias + bcol + 64 + (tc << 2));
    float bsv[8] = {bb0.x, bb0.y, bb0.z, bb0.w, bb1.x, bb1.y, bb1.z, bb1.w};
    #pragma unroll
    for (int half = 0; half < 2; ++half) {
        #pragma unroll
        for (int i = 0; i < 4; ++i) {
            int ii = half * 4 + i;
            int gr = brow + half * 64 + (tr << 2) + i;
            if (gr < NN) {
                float* orow = g_relu + (size_t)gr * HID + bcol;
                unsigned lo, hi;
                float v[8];
                #pragma unroll
                for (int j = 0; j < 4; ++j) {
                    UNPACK2(lo, hi, acc2[ii][j]);
                    v[2 * j]     = __uint_as_float(lo);
                    v[2 * j + 1] = __uint_as_float(hi);
                }
                float4 o0, o1;
                o0.x = fmaxf(v[0] + bsv[0], 0.f);
                o0.y = fmaxf(v[1] + bsv[1], 0.f);
                o0.z = fmaxf(v[2] + bsv[2], 0.f);
                o0.w = fmaxf(v[3] + bsv[3], 0.f);
                o1.x = fmaxf(v[4] + bsv[4], 0.f);
                o1.y = fmaxf(v[5] + bsv[5], 0.f);
                o1.z = fmaxf(v[6] + bsv[6], 0.f);
                o1.w = fmaxf(v[7] + bsv[7], 0.f);
                *(float4*)(orow + (tc << 2))      = o0;
                *(float4*)(orow + 64 + (tc << 2)) = o1;
            }
        }
    }
}

// ---------------- GEMM2: g_h = g_relu @ W2 + b2; seed r_K = temp[K]*h -------
// 128-row tile (grid 391 -> 2.6 waves), 256 threads, 4 rows x 6 cols/thread.
#define G2KC 32
__global__ void __launch_bounds__(256)
k_gemm2(const float* __restrict__ W, const float* __restrict__ bias,
        const float* __restrict__ temp) {
    __shared__ __align__(16) float Ws[G2KC * 48];     // 6 KB
    __shared__ __align__(16) float As[G2KC][132];     // k-major, pad 132
    int tid  = threadIdx.x;
    int row0 = blockIdx.x * 128;
    int rg = tid >> 3;    // 0..31 -> rows rg*4..rg*4+3
    int cg = tid & 7;     // cols cg*6..cg*6+5

    u64 acc2[4][3];
    #pragma unroll
    for (int i = 0; i < 4; ++i)
        #pragma unroll
        for (int j = 0; j < 3; ++j) acc2[i][j] = 0ull;

    for (int kb = 0; kb < HID; kb += G2KC) {
        __syncthreads();
        #pragma unroll
        for (int j = 0; j < 6; ++j) {
            int li = tid + j * 256;       // < 1536
            Ws[li] = W[kb * 48 + li];
        }
        #pragma unroll
        for (int j = 0; j < 4; ++j) {
            int f = tid + j * 256;        // < 1024 float4 loads
            int row = f >> 3;
            int q = f & 7;
            int gr = row0 + row;
            float4 v = (gr < NN) ? *(const float4*)(g_relu + (size_t)gr * HID + kb + q * 4)
                                 : make_float4(0.f, 0.f, 0.f, 0.f);
            As[q * 4 + 0][row] = v.x;
            As[q * 4 + 1][row] = v.y;
            As[q * 4 + 2][row] = v.z;
            As[q * 4 + 3][row] = v.w;
        }
        __syncthreads();
        #pragma unroll 4
        for (int k = 0; k < G2KC; ++k) {
            const float* wrow = Ws + k * 48 + cg * 6;
            u64 wp0 = *(const u64*)(wrow);
            u64 wp1 = *(const u64*)(wrow + 2);
            u64 wp2 = *(const u64*)(wrow + 4);
            float4 a0 = *(const float4*)&As[k][rg << 2];
            float av[4] = {a0.x, a0.y, a0.z, a0.w};
            #pragma unroll
            for (int i = 0; i < 4; ++i) {
                u64 aa;
                PACK_DUP(aa, av[i]);
                FMA2(acc2[i][0], aa, wp0);
                FMA2(acc2[i][1], aa, wp1);
                FMA2(acc2[i][2], aa, wp2);
            }
        }
    }

    float tK = __ldg(temp + KHOP);     // (1-alpha)^K
    __half* rf = (__half*)g_rf0;
    float bs[6];
    #pragma unroll
    for (int j = 0; j < 6; ++j) bs[j] = bias[cg * 6 + j];
    #pragma unroll
    for (int i = 0; i < 4; ++i) {
        int gr = row0 + rg * 4 + i;
        if (gr < NN) {
            unsigned lo, hi;
            #pragma unroll
            for (int j = 0; j < 3; ++j) {
                UNPACK2(lo, hi, acc2[i][j]);
                float v0 = __uint_as_float(lo) + bs[2 * j];
                float v1 = __uint_as_float(hi) + bs[2 * j + 1];
                int c = cg * 6 + 2 * j;
                g_h[(size_t)gr * 48 + c]     = v0;
                g_h[(size_t)gr * 48 + c + 1] = v1;
                rf[(size_t)gr * 48 + c]     = __float2half_rn(tK * v0);
                rf[(size_t)gr * 48 + c + 1] = __float2half_rn(tK * v1);
            }
        }
    }
}

// ---------------- propagation (Horner): r_k = temp[k]*h + H r_{k+1} ---------
__global__ void __launch_bounds__(192)
k_prop(const float* __restrict__ temp, int k, int srcbuf,
       float* __restrict__ out) {
    int tid  = threadIdx.x;
    int t    = blockIdx.x * 192 + tid;
    int node = t / 12;
    int fx   = t - node * 12;
    int ln   = tid / 12;          // node slot within block (0..15)

    const uint2* __restrict__ cur = srcbuf ? g_rf1 : g_rf0;
    uint2*       __restrict__ nxt = srcbuf ? g_rf0 : g_rf1;

    int beg = g_rowptr[node], end = g_rowptr[node + 1];
    float4 acc = make_float4(0.f, 0.f, 0.f, 0.f);
    const int2* ed = (const int2*)g_edges;
    #pragma unroll 4
    for (int p = beg; p < end; ++p) {
        int2 e = ed[p];
        float w = __int_as_float(e.y);
        uint2 v = __ldg(&cur[e.x * 12 + fx]);
        __half2 h0 = *reinterpret_cast<__half2*>(&v.x);
        __half2 h1 = *reinterpret_cast<__half2*>(&v.y);
        float2 f0 = __half22float2(h0);
        float2 f1 = __half22float2(h1);
        acc.x = fmaf(w, f0.x, acc.x);
        acc.y = fmaf(w, f0.y, acc.y);
        acc.z = fmaf(w, f1.x, acc.z);
        acc.w = fmaf(w, f1.y, acc.w);
    }
    float g = __ldg(temp + k);
    float4 hv = *(const float4*)(g_h + (size_t)node * 48 + fx * 4);
    float4 r;
    r.x = fmaf(g, hv.x, acc.x);
    r.y = fmaf(g, hv.y, acc.y);
    r.z = fmaf(g, hv.z, acc.z);
    r.w = fmaf(g, hv.w, acc.w);

    if (k != 0) {
        __half2 o0 = __floats2half2_rn(r.x, r.y);
        __half2 o1 = __floats2half2_rn(r.z, r.w);
        uint2 o;
        o.x = *reinterpret_cast<unsigned*>(&o0);
        o.y = *reinterpret_cast<unsigned*>(&o1);
        nxt[node * 12 + fx] = o;
        return;
    }

    // ---- k == 0: fused log-softmax over the node's 48 values ----
    __shared__ float pm[16][12];
    __shared__ float ps[16][12];
    __shared__ float red[16];
    float lmax = fmaxf(fmaxf(r.x, r.y), fmaxf(r.z, r.w));
    pm[ln][fx] = lmax;
    __syncthreads();
    if (fx == 0) {
        float m = pm[ln][0];
        #pragma unroll
        for (int j = 1; j < 12; ++j) m = fmaxf(m, pm[ln][j]);
        red[ln] = m;
    }
    __syncthreads();
    float m = red[ln];
    float es = expf(r.x - m) + expf(r.y - m) + expf(r.z - m) + expf(r.w - m);
    ps[ln][fx] = es;
    __syncthreads();
    if (fx == 0) {
        float ssum = 0.f;
        #pragma unroll
        for (int j = 0; j < 12; ++j) ssum += ps[ln][j];
        red[ln] = m + logf(ssum);
    }
    __syncthreads();
    float lse = red[ln];
    float4 o;
    o.x = r.x - lse;
    o.y = r.y - lse;
    o.z = r.z - lse;
    o.w = r.w - lse;
    *(float4*)(out + (size_t)node * 48 + fx * 4) = o;
}

// ---------------- launch ----------------------------------------------------
extern "C" void kernel_launch(void* const* d_in, const int* in_sizes, int n_in,
                              void* d_out, int out_size) {
    const float* x    = (const float*)d_in[0];
    const int*   ei   = (const int*)d_in[1];      // int32 [2, EE]
    const float* W1   = (const float*)d_in[2];
    const float* b1   = (const float*)d_in[3];
    const float* W2   = (const float*)d_in[4];
    const float* b2   = (const float*)d_in[5];
    const float* temp = (const float*)d_in[6];
    float* out = (float*)d_out;
    (void)in_sizes; (void)n_in; (void)out_size;

    // Lazily-created side stream + fork/join events (host handles only; no
    // device memory). Behavior is identical on every call.
    static cudaStream_t s2 = nullptr;
    static cudaEvent_t evFork = nullptr, evJoin = nullptr;
    if (s2 == nullptr) {
        cudaStreamCreateWithFlags(&s2, cudaStreamNonBlocking);
        cudaEventCreateWithFlags(&evFork, cudaEventDisableTiming);
        cudaEventCreateWithFlags(&evJoin, cudaEventDisableTiming);
    }

    // Fork: CSR build (independent of MLP) runs on s2, MLP on the capture
    // stream. Join before propagation (needs both).
    cudaEventRecord(evFork, 0);
    cudaStreamWaitEvent(s2, evFork, 0);

    // CSR branch on s2
    k_init_deg<<<(NN + 255) / 256, 256, 0, s2>>>();
    k_count<<<(EE + 255) / 256, 256, 0, s2>>>(ei);
    k_scan1<<<NBS, 256, 0, s2>>>();
    k_scan3<<<NBS, 256, 0, s2>>>();
    k_fill<<<(EE + NN + 255) / 256, 256, 0, s2>>>(ei);
    cudaEventRecord(evJoin, s2);

    // MLP branch on the main (capture) stream
    dim3 g1((HID + 127) / 128, (NN + 127) / 128);
    k_gemm1<<<g1, 256>>>(x, W1, b1);
    k_gemm2<<<(NN + 127) / 128, 256>>>(W2, b2, temp);

    // Join
    cudaStreamWaitEvent(0, evJoin, 0);

    // Horner propagation: r_k = temp[k]*h + H r_{k+1}, k = K-1 .. 0
    // (k = 0 writes log-softmaxed output directly)
    for (int k = KHOP - 1; k >= 0; --k) {
        int s = KHOP - k;                       // step number 1..K
        int srcbuf = (s & 1) ? 0 : 1;           // r_{k+1} location
        k_prop<<<(NN * 12) / 192, 192>>>(temp, k, srcbuf, out);
    }
}

// round 16
// speedup vs baseline: 1.2426x; 1.0693x over previous
#include <cuda_runtime.h>
#include <cuda_fp16.h>
#include <cstdint>

// Problem constants (fixed by the dataset)
#define NN   50000
#define EE   1600000
#define EN   1650000      // EE + NN self loops
#define IND  256
#define HID  256
#define OUTD 48
#define KHOP 10
#define NBS  196          // ceil(NN/256) scan blocks

typedef unsigned long long u64;

// Packed fp32x2 FMA: d = a*b + d (elementwise on 2 packed floats)
#define FMA2(acc, a, b) \
    asm("fma.rn.f32x2 %0, %1, %2, %0;" : "+l"(acc) : "l"(a), "l"(b))
#define PACK_DUP(out, f) do { \
    unsigned _u = __float_as_uint(f); \
    asm("mov.b64 %0, {%1, %1};" : "=l"(out) : "r"(_u)); \
} while (0)
#define UNPACK2(lo, hi, in) \
    asm("mov.b64 {%0, %1}, %2;" : "=r"(lo), "=r"(hi) : "l"(in))

// ---------------- scratch (device globals; no allocation allowed) ----------
__device__ float     g_relu[NN * HID];    // relu(x@W1+b1)
__device__ float     g_h[NN * OUTD];      // MLP output h (fp32)
__device__ uint2     g_rf0[NN * 12];      // fp16 r ping (48 halves per node)
__device__ uint2     g_rf1[NN * 12];      // fp16 r pong
__device__ int       g_deg[NN];
__device__ int       g_scan[NN];
__device__ int       g_bsum[256];
__device__ int       g_rowptr[NN + 1];
__device__ int       g_cursor[NN];
__device__ float     g_dinv[NN];
__device__ long long g_edges[EN];         // packed {src:int32 (lo), norm:f32 (hi)}

// ---------------- CSR build -------------------------------------------------
__global__ void k_init_deg() {
    int i = blockIdx.x * blockDim.x + threadIdx.x;
    if (i < NN) g_deg[i] = 1;   // self loop
}

__global__ void k_count(const int* __restrict__ ei) {
    int i = blockIdx.x * blockDim.x + threadIdx.x;
    if (i < EE) {
        int d = ei[EE + i];
        if ((unsigned)d < NN) atomicAdd(&g_deg[d], 1);
    }
}

__global__ void k_scan1() {
    __shared__ int s[256];
    int tx = threadIdx.x;
    int i = blockIdx.x * 256 + tx;
    int v = (i < NN) ? g_deg[i] : 0;
    s[tx] = v;
    __syncthreads();
    #pragma unroll
    for (int off = 1; off < 256; off <<= 1) {
        int add = (tx >= off) ? s[tx - off] : 0;
        __syncthreads();
        s[tx] += add;
        __syncthreads();
    }
    if (i < NN) g_scan[i] = s[tx];
    if (tx == 255) g_bsum[blockIdx.x] = s[255];
}

// scan of block sums fused in: each block redundantly scans g_bsum in smem
// and extracts its own exclusive offset.
__global__ void k_scan3() {
    __shared__ int s[256];
    int tx = threadIdx.x;
    int b  = blockIdx.x;
    int bv = (tx < NBS) ? g_bsum[tx] : 0;
    s[tx] = bv;
    __syncthreads();
    #pragma unroll
    for (int off = 1; off < 256; off <<= 1) {
        int add = (tx >= off) ? s[tx - off] : 0;
        __syncthreads();
        s[tx] += add;
        __syncthreads();
    }
    int boff = s[b] - g_bsum[b];   // exclusive offset of this block's chunk
    int i = b * 256 + tx;
    if (i >= NN) return;
    int incl = g_scan[i] + boff;
    g_rowptr[i + 1] = incl;
    g_cursor[i] = incl - g_deg[i];           // exclusive start
    g_dinv[i] = rsqrtf((float)g_deg[i]);     // deg >= 1 always
    if (i == 0) g_rowptr[0] = 0;
}

__global__ void k_fill(const int* __restrict__ ei) {
    int i = blockIdx.x * blockDim.x + threadIdx.x;
    if (i >= EN) return;
    int s, d;
    if (i < EE) { s = ei[i]; d = ei[EE + i]; }
    else        { s = i - EE; d = s; }
    if ((unsigned)s >= NN || (unsigned)d >= NN) return;
    float w = g_dinv[s] * g_dinv[d];
    int pos = atomicAdd(&g_cursor[d], 1);
    g_edges[pos] = (long long)(unsigned)s |
                   ((long long)__float_as_uint(w) << 32);
}

// ---------------- GEMM1: g_relu = relu(x @ W1 + b1) -------------------------
// 128x128 tile, 256 threads, 8x8 per thread, packed f32x2 FMAs.
// (R7 configuration — best measured: 144.8 us.)
#define KC 16
__global__ void __launch_bounds__(256, 2)
k_gemm1(const float* __restrict__ A, const float* __restrict__ B,
        const float* __restrict__ bias) {
    __shared__ __align__(16) float As[KC][132];   // transposed A tile (k-major)
    __shared__ __align__(16) float Bs[KC][132];
    int tid  = threadIdx.x;
    int brow = blockIdx.y * 128;
    int bcol = blockIdx.x * 128;
    int tr = tid >> 4, tc = tid & 15;

    int arow = tid >> 1;
    int ak   = (tid & 1) << 3;
    int grow = brow + arow;
    bool aok = grow < NN;
    const float* aptr = A + (size_t)grow * IND + ak;
    int bk = tid >> 4;
    int bc = (tid & 15) << 3;
    const float* bptr = B + bk * HID + bcol + bc;

    float4 pa0, pa1, pb0, pb1;
    const float4 z4 = make_float4(0.f, 0.f, 0.f, 0.f);
    pa0 = aok ? *(const float4*)(aptr)     : z4;
    pa1 = aok ? *(const float4*)(aptr + 4) : z4;
    pb0 = *(const float4*)(bptr);
    pb1 = *(const float4*)(bptr + 4);

    u64 acc2[8][4];   // 8 rows x 4 col-pairs
    #pragma unroll
    for (int i = 0; i < 8; ++i)
        #pragma unroll
        for (int j = 0; j < 4; ++j) acc2[i][j] = 0ull;

    #pragma unroll 1
    for (int c = 0; c < IND / KC; ++c) {
        __syncthreads();
        As[ak + 0][arow] = pa0.x;
        As[ak + 1][arow] = pa0.y;
        As[ak + 2][arow] = pa0.z;
        As[ak + 3][arow] = pa0.w;
        As[ak + 4][arow] = pa1.x;
        As[ak + 5][arow] = pa1.y;
        As[ak + 6][arow] = pa1.z;
        As[ak + 7][arow] = pa1.w;
        *(float4*)&Bs[bk][bc]     = pb0;
        *(float4*)&Bs[bk][bc + 4] = pb1;
        __syncthreads();
        if (c + 1 < IND / KC) {
            const float* ap = aptr + (c + 1) * KC;
            pa0 = aok ? *(const float4*)(ap)     : z4;
            pa1 = aok ? *(const float4*)(ap + 4) : z4;
            const float* bp = bptr + (c + 1) * KC * HID;
            pb0 = *(const float4*)(bp);
            pb1 = *(const float4*)(bp + 4);
        }
        #pragma unroll
        for (int k = 0; k < KC; ++k) {
            float4 a0 = *(const float4*)&As[k][tr << 2];
            float4 a1 = *(const float4*)&As[k][64 + (tr << 2)];
            ulonglong2 bq0 = *(const ulonglong2*)&Bs[k][tc << 2];
            ulonglong2 bq1 = *(const ulonglong2*)&Bs[k][64 + (tc << 2)];
            u64 bp2[4] = {bq0.x, bq0.y, bq1.x, bq1.y};
            float av[8] = {a0.x, a0.y, a0.z, a0.w, a1.x, a1.y, a1.z, a1.w};
            #pragma unroll
            for (int i = 0; i < 8; ++i) {
                u64 aa;
                PACK_DUP(aa, av[i]);
                #pragma unroll
                for (int j = 0; j < 4; ++j) FMA2(acc2[i][j], aa, bp2[j]);
            }
        }
    }

    float4 bb0 = *(const float4*)(bias + bcol + (tc << 2));
    float4 bb1 = *(const float4*)(bias + bcol + 64 + (tc << 2));
    float bsv[8] = {bb0.x, bb0.y, bb0.z, bb0.w, bb1.x, bb1.y, bb1.z, bb1.w};
    #pragma unroll
    for (int half = 0; half < 2; ++half) {
        #pragma unroll
        for (int i = 0; i < 4; ++i) {
            int ii = half * 4 + i;
            int gr = brow + half * 64 + (tr << 2) + i;
            if (gr < NN) {
                float* orow = g_relu + (size_t)gr * HID + bcol;
                unsigned lo, hi;
                float v[8];
                #pragma unroll
                for (int j = 0; j < 4; ++j) {
                    UNPACK2(lo, hi, acc2[ii][j]);
                    v[2 * j]     = __uint_as_float(lo);
                    v[2 * j + 1] = __uint_as_float(hi);
                }
                float4 o0, o1;
                o0.x = fmaxf(v[0] + bsv[0], 0.f);
                o0.y = fmaxf(v[1] + bsv[1], 0.f);
                o0.z = fmaxf(v[2] + bsv[2], 0.f);
                o0.w = fmaxf(v[3] + bsv[3], 0.f);
                o1.x = fmaxf(v[4] + bsv[4], 0.f);
                o1.y = fmaxf(v[5] + bsv[5], 0.f);
                o1.z = fmaxf(v[6] + bsv[6], 0.f);
                o1.w = fmaxf(v[7] + bsv[7], 0.f);
                *(float4*)(orow + (tc << 2))      = o0;
                *(float4*)(orow + 64 + (tc << 2)) = o1;
            }
        }
    }
}

// ---------------- GEMM2: g_h = g_relu @ W2 + b2; seed r_K = temp[K]*h -------
// 128-row tile (grid 391 -> 2.6 waves), 256 threads, 4 rows x 6 cols/thread.
#define G2KC 32
__global__ void __launch_bounds__(256)
k_gemm2(const float* __restrict__ W, const float* __restrict__ bias,
        const float* __restrict__ temp) {
    __shared__ __align__(16) float Ws[G2KC * 48];     // 6 KB
    __shared__ __align__(16) float As[G2KC][132];     // k-major, pad 132
    int tid  = threadIdx.x;
    int row0 = blockIdx.x * 128;
    int rg = tid >> 3;    // 0..31 -> rows rg*4..rg*4+3
    int cg = tid & 7;     // cols cg*6..cg*6+5

    u64 acc2[4][3];
    #pragma unroll
    for (int i = 0; i < 4; ++i)
        #pragma unroll
        for (int j = 0; j < 3; ++j) acc2[i][j] = 0ull;

    for (int kb = 0; kb < HID; kb += G2KC) {
        __syncthreads();
        #pragma unroll
        for (int j = 0; j < 6; ++j) {
            int li = tid + j * 256;       // < 1536
            Ws[li] = W[kb * 48 + li];
        }
        #pragma unroll
        for (int j = 0; j < 4; ++j) {
            int f = tid + j * 256;        // < 1024 float4 loads
            int row = f >> 3;
            int q = f & 7;
            int gr = row0 + row;
            float4 v = (gr < NN) ? *(const float4*)(g_relu + (size_t)gr * HID + kb + q * 4)
                                 : make_float4(0.f, 0.f, 0.f, 0.f);
            As[q * 4 + 0][row] = v.x;
            As[q * 4 + 1][row] = v.y;
            As[q * 4 + 2][row] = v.z;
            As[q * 4 + 3][row] = v.w;
        }
        __syncthreads();
        #pragma unroll 4
        for (int k = 0; k < G2KC; ++k) {
            const float* wrow = Ws + k * 48 + cg * 6;
            u64 wp0 = *(const u64*)(wrow);
            u64 wp1 = *(const u64*)(wrow + 2);
            u64 wp2 = *(const u64*)(wrow + 4);
            float4 a0 = *(const float4*)&As[k][rg << 2];
            float av[4] = {a0.x, a0.y, a0.z, a0.w};
            #pragma unroll
            for (int i = 0; i < 4; ++i) {
                u64 aa;
                PACK_DUP(aa, av[i]);
                FMA2(acc2[i][0], aa, wp0);
                FMA2(acc2[i][1], aa, wp1);
                FMA2(acc2[i][2], aa, wp2);
            }
        }
    }

    float tK = __ldg(temp + KHOP);     // (1-alpha)^K
    __half* rf = (__half*)g_rf0;
    float bs[6];
    #pragma unroll
    for (int j = 0; j < 6; ++j) bs[j] = bias[cg * 6 + j];
    #pragma unroll
    for (int i = 0; i < 4; ++i) {
        int gr = row0 + rg * 4 + i;
        if (gr < NN) {
            unsigned lo, hi;
            #pragma unroll
            for (int j = 0; j < 3; ++j) {
                UNPACK2(lo, hi, acc2[i][j]);
                float v0 = __uint_as_float(lo) + bs[2 * j];
                float v1 = __uint_as_float(hi) + bs[2 * j + 1];
                int c = cg * 6 + 2 * j;
                g_h[(size_t)gr * 48 + c]     = v0;
                g_h[(size_t)gr * 48 + c + 1] = v1;
                rf[(size_t)gr * 48 + c]     = __float2half_rn(tK * v0);
                rf[(size_t)gr * 48 + c + 1] = __float2half_rn(tK * v1);
            }
        }
    }
}

// ---------------- propagation (Horner): r_k = temp[k]*h + H r_{k+1} ---------
// 12 threads per node, 16 nodes per 192-thread block. The block's CSR edge
// records are CONTIGUOUS — stage them into smem with coalesced loads, then
// the gather loop reads edges from LDS (no dependent L2 chain) and issues
// gathers back-to-back. CAP overflow (~10 sigma) falls back to global reads.
#define ECAP 768
__global__ void __launch_bounds__(192)
k_prop(const float* __restrict__ temp, int k, int srcbuf,
       float* __restrict__ out) {
    __shared__ __align__(16) int2 se[ECAP];
    int tid  = threadIdx.x;
    int n0   = blockIdx.x * 16;
    int node = n0 + tid / 12;
    int fx   = tid - (tid / 12) * 12;
    int ln   = tid / 12;          // node slot within block (0..15)

    const uint2* __restrict__ cur = srcbuf ? g_rf1 : g_rf0;
    uint2*       __restrict__ nxt = srcbuf ? g_rf0 : g_rf1;
    const int2* __restrict__ ed = (const int2*)g_edges;

    int base  = g_rowptr[n0];
    int tot   = g_rowptr[n0 + 16] - base;
    int staged = tot < ECAP ? tot : ECAP;

    // Cooperative coalesced stage of this block's edge records
    for (int i = tid; i < staged; i += 192) se[i] = ed[base + i];

    int beg = g_rowptr[node] - base;
    int end = g_rowptr[node + 1] - base;
    __syncthreads();

    float4 acc = make_float4(0.f, 0.f, 0.f, 0.f);
    int mid = end < staged ? end : staged;
    #pragma unroll 4
    for (int p = beg; p < mid; ++p) {
        int2 e = se[p];
        float w = __int_as_float(e.y);
        uint2 v = __ldg(&cur[e.x * 12 + fx]);
        __half2 h0 = *reinterpret_cast<__half2*>(&v.x);
        __half2 h1 = *reinterpret_cast<__half2*>(&v.y);
        float2 f0 = __half22float2(h0);
        float2 f1 = __half22float2(h1);
        acc.x = fmaf(w, f0.x, acc.x);
        acc.y = fmaf(w, f0.y, acc.y);
        acc.z = fmaf(w, f1.x, acc.z);
        acc.w = fmaf(w, f1.y, acc.w);
    }
    // Residual (only if block edge count exceeded ECAP)
    for (int p = (beg > staged ? beg : staged); p < end; ++p) {
        int2 e = ed[base + p];
        float w = __int_as_float(e.y);
        uint2 v = __ldg(&cur[e.x * 12 + fx]);
        __half2 h0 = *reinterpret_cast<__half2*>(&v.x);
        __half2 h1 = *reinterpret_cast<__half2*>(&v.y);
        float2 f0 = __half22float2(h0);
        float2 f1 = __half22float2(h1);
        acc.x = fmaf(w, f0.x, acc.x);
        acc.y = fmaf(w, f0.y, acc.y);
        acc.z = fmaf(w, f1.x, acc.z);
        acc.w = fmaf(w, f1.y, acc.w);
    }

    float g = __ldg(temp + k);
    float4 hv = *(const float4*)(g_h + (size_t)node * 48 + fx * 4);
    float4 r;
    r.x = fmaf(g, hv.x, acc.x);
    r.y = fmaf(g, hv.y, acc.y);
    r.z = fmaf(g, hv.z, acc.z);
    r.w = fmaf(g, hv.w, acc.w);

    if (k != 0) {
        __half2 o0 = __floats2half2_rn(r.x, r.y);
        __half2 o1 = __floats2half2_rn(r.z, r.w);
        uint2 o;
        o.x = *reinterpret_cast<unsigned*>(&o0);
        o.y = *reinterpret_cast<unsigned*>(&o1);
        nxt[node * 12 + fx] = o;
        return;
    }

    // ---- k == 0: fused log-softmax over the node's 48 values ----
    __shared__ float pm[16][12];
    __shared__ float ps[16][12];
    __shared__ float red[16];
    float lmax = fmaxf(fmaxf(r.x, r.y), fmaxf(r.z, r.w));
    pm[ln][fx] = lmax;
    __syncthreads();
    if (fx == 0) {
        float m = pm[ln][0];
        #pragma unroll
        for (int j = 1; j < 12; ++j) m = fmaxf(m, pm[ln][j]);
        red[ln] = m;
    }
    __syncthreads();
    float m = red[ln];
    float es = expf(r.x - m) + expf(r.y - m) + expf(r.z - m) + expf(r.w - m);
    ps[ln][fx] = es;
    __syncthreads();
    if (fx == 0) {
        float ssum = 0.f;
        #pragma unroll
        for (int j = 0; j < 12; ++j) ssum += ps[ln][j];
        red[ln] = m + logf(ssum);
    }
    __syncthreads();
    float lse = red[ln];
    float4 o;
    o.x = r.x - lse;
    o.y = r.y - lse;
    o.z = r.z - lse;
    o.w = r.w - lse;
    *(float4*)(out + (size_t)node * 48 + fx * 4) = o;
}

// ---------------- launch ----------------------------------------------------
extern "C" void kernel_launch(void* const* d_in, const int* in_sizes, int n_in,
                              void* d_out, int out_size) {
    const float* x    = (const float*)d_in[0];
    const int*   ei   = (const int*)d_in[1];      // int32 [2, EE]
    const float* W1   = (const float*)d_in[2];
    const float* b1   = (const float*)d_in[3];
    const float* W2   = (const float*)d_in[4];
    const float* b2   = (const float*)d_in[5];
    const float* temp = (const float*)d_in[6];
    float* out = (float*)d_out;
    (void)in_sizes; (void)n_in; (void)out_size;

    // Lazily-created side stream + fork/join events (host handles only; no
    // device memory). Behavior is identical on every call.
    static cudaStream_t s2 = nullptr;
    static cudaEvent_t evFork = nullptr, evJoin = nullptr;
    if (s2 == nullptr) {
        cudaStreamCreateWithFlags(&s2, cudaStreamNonBlocking);
        cudaEventCreateWithFlags(&evFork, cudaEventDisableTiming);
        cudaEventCreateWithFlags(&evJoin, cudaEventDisableTiming);
    }

    // Fork: CSR build (independent of MLP) runs on s2, MLP on the capture
    // stream. Join before propagation (needs both).
    cudaEventRecord(evFork, 0);
    cudaStreamWaitEvent(s2, evFork, 0);

    // CSR branch on s2
    k_init_deg<<<(NN + 255) / 256, 256, 0, s2>>>();
    k_count<<<(EE + 255) / 256, 256, 0, s2>>>(ei);
    k_scan1<<<NBS, 256, 0, s2>>>();
    k_scan3<<<NBS, 256, 0, s2>>>();
    k_fill<<<(EE + NN + 255) / 256, 256, 0, s2>>>(ei);
    cudaEventRecord(evJoin, s2);

    // MLP branch on the main (capture) stream
    dim3 g1((HID + 127) / 128, (NN + 127) / 128);
    k_gemm1<<<g1, 256>>>(x, W1, b1);
    k_gemm2<<<(NN + 127) / 128, 256>>>(W2, b2, temp);

    // Join
    cudaStreamWaitEvent(0, evJoin, 0);

    // Horner propagation: r_k = temp[k]*h + H r_{k+1}, k = K-1 .. 0
    // (k = 0 writes log-softmaxed output directly)
    for (int k = KHOP - 1; k >= 0; --k) {
        int s = KHOP - k;                       // step number 1..K
        int srcbuf = (s & 1) ? 0 : 1;           // r_{k+1} location
        k_prop<<<(NN * 12) / 192, 192>>>(temp, k, srcbuf, out);
    }
}